// round 1
// baseline (speedup 1.0000x reference)
#include <cuda_runtime.h>
#include <cuda_bf16.h>
#include <cstdint>

// Problem constants
#define BB 8
#define HH 128
#define WW 128
#define CC 96
#define NPIX (HH*WW)           // 16384
#define TH 16
#define TW 8

// -------- scratch (device globals; no allocations allowed) --------
__device__ float g_q[(size_t)BB*NPIX*CC];
__device__ float g_k[(size_t)BB*NPIX*CC];
__device__ float g_v[(size_t)BB*NPIX*CC];
__device__ float g_spat[(size_t)BB*NPIX];
__device__ float g_sums[BB*3*CC];   // [b][{pl,pp,ll}][c]
__device__ float g_chan[BB*CC];

// ----------------------------------------------------------------------
// Kernel A: 3x3 SAME conv (NHWC, C=96->96) + inference BN + sigmoid
// Block: 256 threads computes a TH x TW = 16x8 pixel tile x all 96 couts.
// Thread: 4 pixels x 12 couts register tile.
// smem: input halo [96 cin][18*10 pos] + per-tap weights [96 cin][96 cout]
// ----------------------------------------------------------------------
__global__ __launch_bounds__(256, 2) void conv_bn_sig_kernel(
    const float* __restrict__ x, const float* __restrict__ w,
    const float* __restrict__ gam, const float* __restrict__ bet,
    const float* __restrict__ mu, const float* __restrict__ var,
    float* __restrict__ out)
{
    extern __shared__ float smem[];
    float* s_in = smem;                 // 96*180 floats = 69120 B
    float* s_w  = smem + CC * 180;      // 96*96  floats = 36864 B

    const int bt = blockIdx.z;
    const int h0 = blockIdx.y * TH;
    const int w0 = blockIdx.x * TW;
    const int tid = threadIdx.x;

    // ---- load input halo: rows h0-1..h0+16, cols w0-1..w0+8, 96 ch ----
    // 180 positions * 24 float4-groups of channels
    for (int i = tid; i < 180 * 24; i += 256) {
        int pos = i / 24;
        int cg4 = i % 24;
        int r = pos / 10, c = pos % 10;
        int gh = h0 + r - 1, gw = w0 + c - 1;
        float4 val = make_float4(0.f, 0.f, 0.f, 0.f);
        if (gh >= 0 && gh < HH && gw >= 0 && gw < WW) {
            val = *reinterpret_cast<const float4*>(
                x + (((size_t)bt * HH + gh) * WW + gw) * CC + cg4 * 4);
        }
        int cb = cg4 * 4;
        s_in[(cb + 0) * 180 + pos] = val.x;
        s_in[(cb + 1) * 180 + pos] = val.y;
        s_in[(cb + 2) * 180 + pos] = val.z;
        s_in[(cb + 3) * 180 + pos] = val.w;
    }

    const int pg = tid & 31;            // pixel group 0..31 (4 pixels each)
    const int cg = tid >> 5;            // cout group 0..7 (12 couts each)
    const int rr = pg >> 1;             // tile row 0..15
    const int ccb = (pg & 1) * 4;       // tile col base {0,4}
    const int coutb = cg * 12;

    float acc[4][12];
    #pragma unroll
    for (int i = 0; i < 4; i++)
        #pragma unroll
        for (int j = 0; j < 12; j++) acc[i][j] = 0.f;

    for (int tap = 0; tap < 9; ++tap) {
        __syncthreads();  // halo ready (tap 0) / previous compute done
        // weights chunk for this tap: HWIO -> [cin][cout] contiguous
        const float4* wsrc = reinterpret_cast<const float4*>(w + (size_t)tap * CC * 96);
        float4* wdst = reinterpret_cast<float4*>(s_w);
        for (int i = tid; i < CC * 96 / 4; i += 256) wdst[i] = wsrc[i];
        __syncthreads();

        const int dh = tap / 3, dw = tap % 3;
        const int abase = (rr + dh) * 10 + ccb + dw;

        #pragma unroll 2
        for (int cin = 0; cin < CC; ++cin) {
            const float* ain = s_in + cin * 180 + abase;
            float a0 = ain[0], a1 = ain[1], a2 = ain[2], a3 = ain[3];
            const float4* wp = reinterpret_cast<const float4*>(s_w + cin * 96 + coutb);
            float4 w0v = wp[0], w1v = wp[1], w2v = wp[2];
            float wv[12] = {w0v.x, w0v.y, w0v.z, w0v.w,
                            w1v.x, w1v.y, w1v.z, w1v.w,
                            w2v.x, w2v.y, w2v.z, w2v.w};
            #pragma unroll
            for (int j = 0; j < 12; j++) {
                acc[0][j] = fmaf(a0, wv[j], acc[0][j]);
                acc[1][j] = fmaf(a1, wv[j], acc[1][j]);
                acc[2][j] = fmaf(a2, wv[j], acc[2][j]);
                acc[3][j] = fmaf(a3, wv[j], acc[3][j]);
            }
        }
    }

    // ---- epilogue: BN + sigmoid, vectorized store ----
    float gg[12], bb2[12], mm[12], rs[12];
    #pragma unroll
    for (int j = 0; j < 12; j++) {
        int co = coutb + j;
        gg[j] = gam[co]; bb2[j] = bet[co]; mm[j] = mu[co];
        rs[j] = rsqrtf(var[co] + 1e-5f);
    }
    #pragma unroll
    for (int i = 0; i < 4; i++) {
        int gh = h0 + rr;
        int gw = w0 + ccb + i;
        float* op = out + (((size_t)bt * HH + gh) * WW + gw) * CC + coutb;
        float res[12];
        #pragma unroll
        for (int j = 0; j < 12; j++) {
            float vbn = (acc[i][j] - mm[j]) * rs[j] * gg[j] + bb2[j];
            res[j] = 1.f / (1.f + __expf(-vbn));
        }
        *reinterpret_cast<float4*>(op + 0) = make_float4(res[0], res[1], res[2], res[3]);
        *reinterpret_cast<float4*>(op + 4) = make_float4(res[4], res[5], res[6], res[7]);
        *reinterpret_cast<float4*>(op + 8) = make_float4(res[8], res[9], res[10], res[11]);
    }
}

// ---- fractal tanimoto from the three reduced sums ----
__device__ __forceinline__ float ftan(float tpl, float tpp, float tll)
{
    float num = tpl + 1e-5f;
    float den = 0.f;
    float a = 1.f;
    #pragma unroll
    for (int d = 0; d < 5; d++) {
        float bcoef = -(2.f * a - 1.f);
        den += 1.f / (a * (tpp + tll) + bcoef * tpl + 1e-5f);
        a *= 2.f;
    }
    return num * den * 0.2f;
}

// ----------------------------------------------------------------------
// zero the channel-sum accumulators
// ----------------------------------------------------------------------
__global__ void zero_sums_kernel()
{
    int i = blockIdx.x * blockDim.x + threadIdx.x;
    if (i < BB * 3 * CC) g_sums[i] = 0.f;
}

// ----------------------------------------------------------------------
// Kernel B: per-pixel spatial attention + per-(b,c) partial sums.
// grid (128, B), block 256 = 8 warps; warp handles 16 pixels.
// lane owns channels {lane, lane+32, lane+64}.
// ----------------------------------------------------------------------
__global__ __launch_bounds__(256) void attn_stats_kernel()
{
    __shared__ float s_sum[3 * CC];
    const int b = blockIdx.y;
    const int lane = threadIdx.x & 31;
    const int warp = threadIdx.x >> 5;

    for (int i = threadIdx.x; i < 3 * CC; i += 256) s_sum[i] = 0.f;
    __syncthreads();

    float aPL[3] = {0, 0, 0}, aPP[3] = {0, 0, 0}, aLL[3] = {0, 0, 0};
    int pix0 = blockIdx.x * 128 + warp * 16;

    for (int t = 0; t < 16; ++t) {
        int pix = pix0 + t;
        const float* qp = g_q + ((size_t)b * NPIX + pix) * CC;
        const float* kp = g_k + ((size_t)b * NPIX + pix) * CC;
        float tpl = 0.f, tpp = 0.f, tll = 0.f;
        #pragma unroll
        for (int s = 0; s < 3; s++) {
            float qv = qp[lane + s * 32];
            float kv = kp[lane + s * 32];
            float pl = qv * kv, pp = qv * qv, ll = kv * kv;
            aPL[s] += pl; aPP[s] += pp; aLL[s] += ll;
            tpl += pl; tpp += pp; tll += ll;
        }
        #pragma unroll
        for (int off = 16; off > 0; off >>= 1) {
            tpl += __shfl_xor_sync(0xffffffffu, tpl, off);
            tpp += __shfl_xor_sync(0xffffffffu, tpp, off);
            tll += __shfl_xor_sync(0xffffffffu, tll, off);
        }
        if (lane == 0)
            g_spat[(size_t)b * NPIX + pix] = ftan(tpl, tpp, tll);
    }

    #pragma unroll
    for (int s = 0; s < 3; s++) {
        int c = lane + s * 32;
        atomicAdd(&s_sum[0 * CC + c], aPL[s]);
        atomicAdd(&s_sum[1 * CC + c], aPP[s]);
        atomicAdd(&s_sum[2 * CC + c], aLL[s]);
    }
    __syncthreads();
    for (int i = threadIdx.x; i < 3 * CC; i += 256)
        atomicAdd(&g_sums[b * 3 * CC + i], s_sum[i]);
}

// ----------------------------------------------------------------------
// Kernel B2: channel attention from the reduced sums (768 values)
// ----------------------------------------------------------------------
__global__ void chan_att_kernel()
{
    int i = blockIdx.x * blockDim.x + threadIdx.x;
    if (i < BB * CC) {
        int b = i / CC, c = i % CC;
        float tpl = g_sums[b * 3 * CC + 0 * CC + c];
        float tpp = g_sums[b * 3 * CC + 1 * CC + c];
        float tll = g_sums[b * 3 * CC + 2 * CC + c];
        g_chan[i] = ftan(tpl, tpp, tll);
    }
}

// ----------------------------------------------------------------------
// Kernel C: out = BN(0.5*(att_chan + att_spat) * v)
// ----------------------------------------------------------------------
__global__ __launch_bounds__(256) void final_kernel(
    const float* __restrict__ gam, const float* __restrict__ bet,
    const float* __restrict__ mu, const float* __restrict__ var,
    float* __restrict__ out)
{
    size_t i = (size_t)blockIdx.x * 256 + threadIdx.x;   // float4 index
    size_t e = i * 4;
    if (e >= (size_t)BB * NPIX * CC) return;
    int c = (int)(e % CC);
    size_t pix = e / CC;
    int b = (int)(pix >> 14);
    float as = g_spat[pix];
    float4 vv4 = *reinterpret_cast<const float4*>(g_v + e);
    float vin[4] = {vv4.x, vv4.y, vv4.z, vv4.w};
    float res[4];
    #pragma unroll
    for (int j = 0; j < 4; j++) {
        int cj = c + j;
        float val = 0.5f * (g_chan[b * CC + cj] + as) * vin[j];
        res[j] = (val - mu[cj]) * rsqrtf(var[cj] + 1e-5f) * gam[cj] + bet[cj];
    }
    *reinterpret_cast<float4*>(out + e) = make_float4(res[0], res[1], res[2], res[3]);
}

// ----------------------------------------------------------------------
extern "C" void kernel_launch(void* const* d_in, const int* in_sizes, int n_in,
                              void* d_out, int out_size)
{
    const float* x1 = (const float*)d_in[0];
    const float* x2 = (const float*)d_in[1];
    const float* x3 = (const float*)d_in[2];
    const float* wq = (const float*)d_in[3];
    const float* gq = (const float*)d_in[4];
    const float* bq = (const float*)d_in[5];
    const float* mq = (const float*)d_in[6];
    const float* vq = (const float*)d_in[7];
    const float* wk = (const float*)d_in[8];
    const float* gk = (const float*)d_in[9];
    const float* bk = (const float*)d_in[10];
    const float* mk = (const float*)d_in[11];
    const float* vk = (const float*)d_in[12];
    const float* wv = (const float*)d_in[13];
    const float* gv = (const float*)d_in[14];
    const float* bv = (const float*)d_in[15];
    const float* mv = (const float*)d_in[16];
    const float* vv = (const float*)d_in[17];
    const float* gn  = (const float*)d_in[18];
    const float* bnb = (const float*)d_in[19];
    const float* mn  = (const float*)d_in[20];
    const float* vn  = (const float*)d_in[21];
    float* out = (float*)d_out;

    float *qp, *kp, *vp;
    cudaGetSymbolAddress((void**)&qp, g_q);
    cudaGetSymbolAddress((void**)&kp, g_k);
    cudaGetSymbolAddress((void**)&vp, g_v);

    const int smemA = (CC * 180 + CC * 96) * sizeof(float);   // 105984 B
    cudaFuncSetAttribute(conv_bn_sig_kernel,
                         cudaFuncAttributeMaxDynamicSharedMemorySize, smemA);

    dim3 gridA(WW / TW, HH / TH, BB);   // (16, 8, 8)
    conv_bn_sig_kernel<<<gridA, 256, smemA>>>(x1, wq, gq, bq, mq, vq, qp);
    conv_bn_sig_kernel<<<gridA, 256, smemA>>>(x2, wk, gk, bk, mk, vk, kp);
    conv_bn_sig_kernel<<<gridA, 256, smemA>>>(x3, wv, gv, bv, mv, vv, vp);

    zero_sums_kernel<<<(BB * 3 * CC + 255) / 256, 256>>>();

    dim3 gridB(128, BB);
    attn_stats_kernel<<<gridB, 256>>>();

    chan_att_kernel<<<(BB * CC + 255) / 256, 256>>>();

    size_t n4 = (size_t)BB * NPIX * CC / 4;
    final_kernel<<<(unsigned)((n4 + 255) / 256), 256>>>(gn, bnb, mn, vn, out);
}

// round 2
// speedup vs baseline: 2.8812x; 2.8812x over previous
#include <cuda_runtime.h>
#include <cuda_bf16.h>
#include <cstdint>

// Problem constants
#define BB 8
#define HH 128
#define WW 128
#define CC 96
#define NPIX (HH*WW)           // 16384

// Conv tile geometry
#define CTH 16                 // image rows per block
#define CTW 8                  // image cols per block
#define SP  100                // halo smem stride (floats) per position row  [pos][cin]
#define WS  104                // weight smem stride (floats) per cin row     [cin][cout]
#define HALO_POS (18*10)       // 180 positions

// -------- scratch (device globals; no allocations allowed) --------
__device__ float g_q[(size_t)BB*NPIX*CC];
__device__ float g_k[(size_t)BB*NPIX*CC];
__device__ float g_v[(size_t)BB*NPIX*CC];
__device__ float g_spat[(size_t)BB*NPIX];
__device__ float g_sums[BB*3*CC];   // [b][{pl,pp,ll}][c]
__device__ float g_chan[BB*CC];

// ---- tf32 helpers ----
__device__ __forceinline__ uint32_t f2tf32(float x) {
    uint32_t u;
    asm("cvt.rna.tf32.f32 %0, %1;" : "=r"(u) : "f"(x));
    return u;
}

__device__ __forceinline__ void mma_tf32(float* d,
    uint32_t a0, uint32_t a1, uint32_t a2, uint32_t a3,
    uint32_t b0, uint32_t b1)
{
    asm volatile(
        "mma.sync.aligned.m16n8k8.row.col.f32.tf32.tf32.f32 "
        "{%0,%1,%2,%3}, {%4,%5,%6,%7}, {%8,%9}, {%0,%1,%2,%3};\n"
        : "+f"(d[0]), "+f"(d[1]), "+f"(d[2]), "+f"(d[3])
        : "r"(a0), "r"(a1), "r"(a2), "r"(a3), "r"(b0), "r"(b1));
}

// ----------------------------------------------------------------------
// Conv 3x3 SAME (NHWC, 96->96) + BN + sigmoid, tf32 tensor cores.
// Block: 256 thr = 8 warps (4 M-warps x 2 N-warps).
// Block tile: 128 pixels (16x8) x 96 couts. Warp: 32 pixels x 48 couts.
// smem: halo [180 pos][100] tf32 + per-tap weights [96 cin][104] tf32.
// ----------------------------------------------------------------------
__global__ __launch_bounds__(256, 2) void conv_mma_kernel(
    const float* __restrict__ x, const float* __restrict__ w,
    const float* __restrict__ gam, const float* __restrict__ bet,
    const float* __restrict__ mu, const float* __restrict__ var,
    float* __restrict__ out)
{
    extern __shared__ uint32_t smem_u[];
    uint32_t* s_in = smem_u;                    // 180*100 = 18000 u32 (72000 B)
    uint32_t* s_w  = smem_u + HALO_POS * SP;    // 96*104  =  9984 u32 (39936 B)

    const int bt = blockIdx.z;
    const int h0 = blockIdx.y * CTH;
    const int w0 = blockIdx.x * CTW;
    const int tid  = threadIdx.x;
    const int warp = tid >> 5;
    const int lane = tid & 31;
    const int q    = lane & 3;      // thread-in-group
    const int gid  = lane >> 2;     // group id 0..7
    const int wm   = warp >> 1;     // M-warp 0..3
    const int wn   = warp & 1;      // N-warp 0..1
    const int n0   = wn * 48;

    // ---- stage halo: rows h0-1..h0+16, cols w0-1..w0+8, all 96 cin ----
    for (int i = tid; i < HALO_POS * 24; i += 256) {
        int pos = i / 24;
        int cg  = i % 24;
        int hr = pos / 10, hc = pos % 10;
        int gh = h0 + hr - 1, gw = w0 + hc - 1;
        float4 val = make_float4(0.f, 0.f, 0.f, 0.f);
        if (gh >= 0 && gh < HH && gw >= 0 && gw < WW) {
            val = *reinterpret_cast<const float4*>(
                x + (((size_t)bt * HH + gh) * WW + gw) * CC + cg * 4);
        }
        uint32_t* dst = s_in + pos * SP + cg * 4;
        dst[0] = f2tf32(val.x); dst[1] = f2tf32(val.y);
        dst[2] = f2tf32(val.z); dst[3] = f2tf32(val.w);
    }

    // accumulators: [mtile][ntile][4]
    float acc[2][6][4];
    #pragma unroll
    for (int mt = 0; mt < 2; mt++)
        #pragma unroll
        for (int j = 0; j < 6; j++)
            #pragma unroll
            for (int e = 0; e < 4; e++) acc[mt][j][e] = 0.f;

    for (int tap = 0; tap < 9; ++tap) {
        __syncthreads();   // halo ready / prior tap reads done
        // stage weights for this tap: HWIO -> [cin][cout]
        const float4* wsrc = reinterpret_cast<const float4*>(w + (size_t)tap * CC * CC);
        for (int i = tid; i < CC * 24; i += 256) {
            int cin = i / 24, cg = i % 24;
            float4 val = wsrc[cin * 24 + cg];
            uint32_t* dst = s_w + cin * WS + cg * 4;
            dst[0] = f2tf32(val.x); dst[1] = f2tf32(val.y);
            dst[2] = f2tf32(val.z); dst[3] = f2tf32(val.w);
        }
        __syncthreads();

        const int dh = tap / 3, dw = tap % 3;

        #pragma unroll 2
        for (int kc = 0; kc < 12; ++kc) {
            // A fragments for both m-tiles
            uint32_t a[2][4];
            #pragma unroll
            for (int mt = 0; mt < 2; mt++) {
                int rr = 4 * wm + 2 * mt + dh;                    // halo row of a0 rows
                int base = (rr * 10 + gid + dw) * SP + kc * 8 + q;
                a[mt][0] = s_in[base];
                a[mt][1] = s_in[base + 10 * SP];                  // image row +1
                a[mt][2] = s_in[base + 4];
                a[mt][3] = s_in[base + 10 * SP + 4];
            }
            // B fragments + MMAs
            #pragma unroll
            for (int j = 0; j < 6; j++) {
                int bb = (kc * 8 + q) * WS + n0 + j * 8 + gid;
                uint32_t b0 = s_w[bb];
                uint32_t b1 = s_w[bb + 4 * WS];
                mma_tf32(acc[0][j], a[0][0], a[0][1], a[0][2], a[0][3], b0, b1);
                mma_tf32(acc[1][j], a[1][0], a[1][1], a[1][2], a[1][3], b0, b1);
            }
        }
    }

    // ---- epilogue: BN + sigmoid, float2 stores ----
    #pragma unroll
    for (int j = 0; j < 6; j++) {
        int c0 = n0 + j * 8 + 2 * q;
        int c1 = c0 + 1;
        float g0 = gam[c0], g1 = gam[c1];
        float be0 = bet[c0], be1 = bet[c1];
        float m0 = mu[c0], m1 = mu[c1];
        float r0 = rsqrtf(var[c0] + 1e-5f), r1 = rsqrtf(var[c1] + 1e-5f);
        #pragma unroll
        for (int mt = 0; mt < 2; mt++) {
            int pbase = wm * 32 + mt * 16 + gid;
            #pragma unroll
            for (int half = 0; half < 2; half++) {
                int p = pbase + half * 8;
                int gh = h0 + (p >> 3);
                int gw = w0 + (p & 7);
                float v0 = acc[mt][j][half * 2 + 0];
                float v1 = acc[mt][j][half * 2 + 1];
                float o0 = (v0 - m0) * r0 * g0 + be0;
                float o1 = (v1 - m1) * r1 * g1 + be1;
                o0 = 1.f / (1.f + __expf(-o0));
                o1 = 1.f / (1.f + __expf(-o1));
                *reinterpret_cast<float2*>(
                    out + (((size_t)bt * HH + gh) * WW + gw) * CC + c0) =
                    make_float2(o0, o1);
            }
        }
    }
}

// ---- fractal tanimoto from the three reduced sums ----
__device__ __forceinline__ float ftan(float tpl, float tpp, float tll)
{
    float num = tpl + 1e-5f;
    float den = 0.f;
    float a = 1.f;
    #pragma unroll
    for (int d = 0; d < 5; d++) {
        float bcoef = -(2.f * a - 1.f);
        den += 1.f / (a * (tpp + tll) + bcoef * tpl + 1e-5f);
        a *= 2.f;
    }
    return num * den * 0.2f;
}

__global__ void zero_sums_kernel()
{
    int i = blockIdx.x * blockDim.x + threadIdx.x;
    if (i < BB * 3 * CC) g_sums[i] = 0.f;
}

// ----------------------------------------------------------------------
// Kernel B: per-pixel spatial attention + per-(b,c) partial sums.
// ----------------------------------------------------------------------
__global__ __launch_bounds__(256) void attn_stats_kernel()
{
    __shared__ float s_sum[3 * CC];
    const int b = blockIdx.y;
    const int lane = threadIdx.x & 31;
    const int warp = threadIdx.x >> 5;

    for (int i = threadIdx.x; i < 3 * CC; i += 256) s_sum[i] = 0.f;
    __syncthreads();

    float aPL[3] = {0, 0, 0}, aPP[3] = {0, 0, 0}, aLL[3] = {0, 0, 0};
    int pix0 = blockIdx.x * 128 + warp * 16;

    for (int t = 0; t < 16; ++t) {
        int pix = pix0 + t;
        const float* qp = g_q + ((size_t)b * NPIX + pix) * CC;
        const float* kp = g_k + ((size_t)b * NPIX + pix) * CC;
        float tpl = 0.f, tpp = 0.f, tll = 0.f;
        #pragma unroll
        for (int s = 0; s < 3; s++) {
            float qv = qp[lane + s * 32];
            float kv = kp[lane + s * 32];
            float pl = qv * kv, pp = qv * qv, ll = kv * kv;
            aPL[s] += pl; aPP[s] += pp; aLL[s] += ll;
            tpl += pl; tpp += pp; tll += ll;
        }
        #pragma unroll
        for (int off = 16; off > 0; off >>= 1) {
            tpl += __shfl_xor_sync(0xffffffffu, tpl, off);
            tpp += __shfl_xor_sync(0xffffffffu, tpp, off);
            tll += __shfl_xor_sync(0xffffffffu, tll, off);
        }
        if (lane == 0)
            g_spat[(size_t)b * NPIX + pix] = ftan(tpl, tpp, tll);
    }

    #pragma unroll
    for (int s = 0; s < 3; s++) {
        int c = lane + s * 32;
        atomicAdd(&s_sum[0 * CC + c], aPL[s]);
        atomicAdd(&s_sum[1 * CC + c], aPP[s]);
        atomicAdd(&s_sum[2 * CC + c], aLL[s]);
    }
    __syncthreads();
    for (int i = threadIdx.x; i < 3 * CC; i += 256)
        atomicAdd(&g_sums[b * 3 * CC + i], s_sum[i]);
}

__global__ void chan_att_kernel()
{
    int i = blockIdx.x * blockDim.x + threadIdx.x;
    if (i < BB * CC) {
        int b = i / CC, c = i % CC;
        float tpl = g_sums[b * 3 * CC + 0 * CC + c];
        float tpp = g_sums[b * 3 * CC + 1 * CC + c];
        float tll = g_sums[b * 3 * CC + 2 * CC + c];
        g_chan[i] = ftan(tpl, tpp, tll);
    }
}

// ----------------------------------------------------------------------
// Kernel C: out = BN(0.5*(att_chan + att_spat) * v)
// ----------------------------------------------------------------------
__global__ __launch_bounds__(256) void final_kernel(
    const float* __restrict__ gam, const float* __restrict__ bet,
    const float* __restrict__ mu, const float* __restrict__ var,
    float* __restrict__ out)
{
    size_t i = (size_t)blockIdx.x * 256 + threadIdx.x;   // float4 index
    size_t e = i * 4;
    if (e >= (size_t)BB * NPIX * CC) return;
    int c = (int)(e % CC);
    size_t pix = e / CC;
    int b = (int)(pix >> 14);
    float as = g_spat[pix];
    float4 vv4 = *reinterpret_cast<const float4*>(g_v + e);
    float vin[4] = {vv4.x, vv4.y, vv4.z, vv4.w};
    float res[4];
    #pragma unroll
    for (int j = 0; j < 4; j++) {
        int cj = c + j;
        float val = 0.5f * (g_chan[b * CC + cj] + as) * vin[j];
        res[j] = (val - mu[cj]) * rsqrtf(var[cj] + 1e-5f) * gam[cj] + bet[cj];
    }
    *reinterpret_cast<float4*>(out + e) = make_float4(res[0], res[1], res[2], res[3]);
}

// ----------------------------------------------------------------------
extern "C" void kernel_launch(void* const* d_in, const int* in_sizes, int n_in,
                              void* d_out, int out_size)
{
    const float* x1 = (const float*)d_in[0];
    const float* x2 = (const float*)d_in[1];
    const float* x3 = (const float*)d_in[2];
    const float* wq = (const float*)d_in[3];
    const float* gq = (const float*)d_in[4];
    const float* bq = (const float*)d_in[5];
    const float* mq = (const float*)d_in[6];
    const float* vq = (const float*)d_in[7];
    const float* wk = (const float*)d_in[8];
    const float* gk = (const float*)d_in[9];
    const float* bk = (const float*)d_in[10];
    const float* mk = (const float*)d_in[11];
    const float* vk = (const float*)d_in[12];
    const float* wv = (const float*)d_in[13];
    const float* gv = (const float*)d_in[14];
    const float* bv = (const float*)d_in[15];
    const float* mv = (const float*)d_in[16];
    const float* vv = (const float*)d_in[17];
    const float* gn  = (const float*)d_in[18];
    const float* bnb = (const float*)d_in[19];
    const float* mn  = (const float*)d_in[20];
    const float* vn  = (const float*)d_in[21];
    float* out = (float*)d_out;

    float *qp, *kp, *vp;
    cudaGetSymbolAddress((void**)&qp, g_q);
    cudaGetSymbolAddress((void**)&kp, g_k);
    cudaGetSymbolAddress((void**)&vp, g_v);

    const int smemA = (HALO_POS * SP + CC * WS) * sizeof(float);   // 111936 B
    cudaFuncSetAttribute(conv_mma_kernel,
                         cudaFuncAttributeMaxDynamicSharedMemorySize, smemA);

    dim3 gridA(WW / CTW, HH / CTH, BB);   // (16, 8, 8)
    conv_mma_kernel<<<gridA, 256, smemA>>>(x1, wq, gq, bq, mq, vq, qp);
    conv_mma_kernel<<<gridA, 256, smemA>>>(x2, wk, gk, bk, mk, vk, kp);
    conv_mma_kernel<<<gridA, 256, smemA>>>(x3, wv, gv, bv, mv, vv, vp);

    zero_sums_kernel<<<(BB * 3 * CC + 255) / 256, 256>>>();

    dim3 gridB(128, BB);
    attn_stats_kernel<<<gridB, 256>>>();

    chan_att_kernel<<<(BB * CC + 255) / 256, 256>>>();

    size_t n4 = (size_t)BB * NPIX * CC / 4;
    final_kernel<<<(unsigned)((n4 + 255) / 256), 256>>>(gn, bnb, mn, vn, out);
}

// round 7
// speedup vs baseline: 5.0340x; 1.7472x over previous
#include <cuda_runtime.h>
#include <cuda_bf16.h>
#include <cstdint>

// Problem constants
#define BB 8
#define HH 128
#define WW 128
#define CC 96
#define NPIX (HH*WW)           // 16384

// conv smem layout (dynamic, bytes)
#define OFF_SCALE 0            // 96 floats
#define OFF_SHIFT 384          // 96 floats
#define OFF_A     768          // halo: 130 pos x 208 B (104 bf16) = 27040
#define OFF_W     27808        // weights: 3 taps x 96 cout x 208 B = 59904
#define SMEM_CONV 87712

// -------- scratch (device globals; no allocations allowed) --------
__device__ float g_q[(size_t)BB*NPIX*CC];
__device__ float g_k[(size_t)BB*NPIX*CC];
__device__ float g_v[(size_t)BB*NPIX*CC];
__device__ float g_spat[(size_t)BB*NPIX];
__device__ float g_sums[BB*3*CC];   // [b][{pl,pp,ll}][c]
__device__ float g_chan[BB*CC];
__device__ __nv_bfloat16 g_wbq[9*CC*CC];   // [tap][cout][cin] bf16
__device__ __nv_bfloat16 g_wbk[9*CC*CC];
__device__ __nv_bfloat16 g_wbv[9*CC*CC];

__device__ __forceinline__ uint32_t smem_u32(const void* p) {
    uint32_t a;
    asm("{ .reg .u64 t; cvta.to.shared.u64 t, %1; cvt.u32.u64 %0, t; }"
        : "=r"(a) : "l"(p));
    return a;
}

__device__ __forceinline__ void ldsm_x4(uint32_t* r, uint32_t addr) {
    asm volatile("ldmatrix.sync.aligned.m8n8.x4.shared.b16 {%0,%1,%2,%3}, [%4];"
        : "=r"(r[0]), "=r"(r[1]), "=r"(r[2]), "=r"(r[3]) : "r"(addr));
}

__device__ __forceinline__ void mma_bf16(float* d, const uint32_t* a,
                                         uint32_t b0, uint32_t b1)
{
    asm volatile(
        "mma.sync.aligned.m16n8k16.row.col.f32.bf16.bf16.f32 "
        "{%0,%1,%2,%3}, {%4,%5,%6,%7}, {%8,%9}, {%0,%1,%2,%3};\n"
        : "+f"(d[0]), "+f"(d[1]), "+f"(d[2]), "+f"(d[3])
        : "r"(a[0]), "r"(a[1]), "r"(a[2]), "r"(a[3]), "r"(b0), "r"(b1));
}

// ----------------------------------------------------------------------
// Weight transpose prepass: w[tap][cin][cout] fp32 -> out[tap][cout][cin] bf16
// ----------------------------------------------------------------------
__global__ void wtrans_kernel(const float* __restrict__ w, __nv_bfloat16* __restrict__ out)
{
    int i = blockIdx.x * 256 + threadIdx.x;
    if (i < 9 * CC * CC) {
        int t = i / (CC * CC), r = i % (CC * CC);
        int co = r / CC, ci = r % CC;
        out[i] = __float2bfloat16(w[t * CC * CC + ci * CC + co]);
    }
}

// ----------------------------------------------------------------------
// Conv 3x3 SAME (NHWC 96->96) + BN + sigmoid.
// bf16 mma.sync m16n8k16 + ldmatrix.x4. CTA = one image row:
// M=128 pixels x N=96 couts; K = 9 taps x 96 cin, grouped by dh
// (halo staged once per dh; dw = +208B smem offset).
// Block 256 thr = 8 warps: 4 M-warps x 2 N-warps; warp tile 32M x 48N.
// ----------------------------------------------------------------------
__global__ __launch_bounds__(256, 2) void conv_mma_kernel(
    const float* __restrict__ x, const __nv_bfloat16* __restrict__ wb,
    const float* __restrict__ gam, const float* __restrict__ bet,
    const float* __restrict__ mu, const float* __restrict__ var,
    float* __restrict__ out)
{
    extern __shared__ char smem[];
    const uint32_t sb = smem_u32(smem);
    const int tid  = threadIdx.x;
    const int warp = tid >> 5;
    const int lane = tid & 31;
    const int h  = blockIdx.x;
    const int bt = blockIdx.y;

    const int wm = warp >> 1;          // M-warp 0..3
    const int wn = warp & 1;           // N-warp 0..1
    const int q   = lane & 3;
    const int gid = lane >> 2;
    const int n0  = wn * 48;

    // ldmatrix per-lane row addressing
    const int tl = lane >> 3, r8 = lane & 7;
    // A tiles: tl&1 -> +8 rows, tl>>1 -> k-half (+16B)
    const int aRow0 = (wm * 32 + ((tl & 1) << 3) + r8) * 208 + ((tl >> 1) << 4);
    const int aRow1 = aRow0 + 16 * 208;
    // B tiles (x4 covers j, j+1): tl>>1 -> j offset, tl&1 -> k-half
    int bRow[3];
    #pragma unroll
    for (int jp = 0; jp < 3; jp++)
        bRow[jp] = (n0 + (2 * jp + (tl >> 1)) * 8 + r8) * 208 + ((tl & 1) << 4);

    if (tid < CC) {
        float sc = gam[tid] * rsqrtf(var[tid] + 1e-5f);
        reinterpret_cast<float*>(smem + OFF_SCALE)[tid] = sc;
        reinterpret_cast<float*>(smem + OFF_SHIFT)[tid] = bet[tid] - mu[tid] * sc;
    }

    float acc[2][6][4];
    #pragma unroll
    for (int mt = 0; mt < 2; mt++)
        #pragma unroll
        for (int j = 0; j < 6; j++)
            #pragma unroll
            for (int e = 0; e < 4; e++) acc[mt][j][e] = 0.f;

    for (int dh = 0; dh < 3; dh++) {
        if (dh) __syncthreads();   // protect previous-group reads

        // ---- stage halo: 130 positions (gw=-1..128) x 96 cin, fp32->bf16 ----
        {
            const int gh = h + dh - 1;
            const bool rok = (gh >= 0) && (gh < HH);
            const float* xrow = x + ((size_t)bt * HH + (rok ? gh : 0)) * WW * CC;
            #pragma unroll
            for (int it = 0; it < 7; it++) {
                int u = tid + it * 256;
                if (u < 1560) {
                    int pos = u / 12, cg = u - pos * 12;
                    int gw = pos - 1;
                    uint4 val = make_uint4(0, 0, 0, 0);
                    if (rok && gw >= 0 && gw < WW) {
                        const float4* s = reinterpret_cast<const float4*>(
                            xrow + (size_t)gw * CC + cg * 8);
                        float4 f0 = s[0], f1 = s[1];
                        __nv_bfloat162 p0 = __float22bfloat162_rn(make_float2(f0.x, f0.y));
                        __nv_bfloat162 p1 = __float22bfloat162_rn(make_float2(f0.z, f0.w));
                        __nv_bfloat162 p2 = __float22bfloat162_rn(make_float2(f1.x, f1.y));
                        __nv_bfloat162 p3 = __float22bfloat162_rn(make_float2(f1.z, f1.w));
                        val.x = *reinterpret_cast<uint32_t*>(&p0);
                        val.y = *reinterpret_cast<uint32_t*>(&p1);
                        val.z = *reinterpret_cast<uint32_t*>(&p2);
                        val.w = *reinterpret_cast<uint32_t*>(&p3);
                    }
                    *reinterpret_cast<uint4*>(smem + OFF_A + pos * 208 + cg * 16) = val;
                }
            }
        }
        // ---- stage weights: taps 3dh..3dh+2, [cout][cin] bf16, 208B rows ----
        {
            const uint4* wsrc = reinterpret_cast<const uint4*>(wb + (size_t)dh * 3 * CC * CC);
            #pragma unroll
            for (int it = 0; it < 14; it++) {
                int u = tid + it * 256;
                if (u < 3456) {
                    int tl2 = u / 1152, rem = u - tl2 * 1152;
                    int co = rem / 12, cg = rem - co * 12;
                    uint4 v = wsrc[(size_t)tl2 * 1152 + co * 12 + cg];   // 1152 uint4 per tap
                    *reinterpret_cast<uint4*>(smem + OFF_W + tl2 * 19968 + co * 208 + cg * 16) = v;
                }
            }
        }
        __syncthreads();

        // ---- compute: 3 dw-taps x 6 k16-chunks ----
        #pragma unroll
        for (int dw = 0; dw < 3; dw++) {
            const uint32_t aB = sb + OFF_A + dw * 208;
            const uint32_t wB = sb + OFF_W + dw * 19968;
            #pragma unroll
            for (int kc = 0; kc < 6; kc++) {
                uint32_t a[2][4], bf[3][4];
                ldsm_x4(a[0], aB + aRow0 + kc * 32);
                ldsm_x4(a[1], aB + aRow1 + kc * 32);
                ldsm_x4(bf[0], wB + bRow[0] + kc * 32);
                ldsm_x4(bf[1], wB + bRow[1] + kc * 32);
                ldsm_x4(bf[2], wB + bRow[2] + kc * 32);
                #pragma unroll
                for (int jp = 0; jp < 3; jp++) {
                    mma_bf16(acc[0][2 * jp + 0], a[0], bf[jp][0], bf[jp][1]);
                    mma_bf16(acc[1][2 * jp + 0], a[1], bf[jp][0], bf[jp][1]);
                    mma_bf16(acc[0][2 * jp + 1], a[0], bf[jp][2], bf[jp][3]);
                    mma_bf16(acc[1][2 * jp + 1], a[1], bf[jp][2], bf[jp][3]);
                }
            }
        }
    }

    // ---- epilogue: BN + sigmoid, float2 stores ----
    const float* ssc = reinterpret_cast<const float*>(smem + OFF_SCALE);
    const float* ssh = reinterpret_cast<const float*>(smem + OFF_SHIFT);
    #pragma unroll
    for (int j = 0; j < 6; j++) {
        int c0 = n0 + j * 8 + 2 * q;
        float s0 = ssc[c0], s1 = ssc[c0 + 1];
        float t0 = ssh[c0], t1 = ssh[c0 + 1];
        #pragma unroll
        for (int mt = 0; mt < 2; mt++) {
            #pragma unroll
            for (int half = 0; half < 2; half++) {
                int p = wm * 32 + mt * 16 + gid + half * 8;   // pixel = gw
                float v0 = acc[mt][j][half * 2 + 0];
                float v1 = acc[mt][j][half * 2 + 1];
                float o0 = v0 * s0 + t0;
                float o1 = v1 * s1 + t1;
                o0 = 1.f / (1.f + __expf(-o0));
                o1 = 1.f / (1.f + __expf(-o1));
                *reinterpret_cast<float2*>(
                    out + (((size_t)bt * HH + h) * WW + p) * CC + c0) =
                    make_float2(o0, o1);
            }
        }
    }
}

// ---- fractal tanimoto from the three reduced sums ----
__device__ __forceinline__ float ftan(float tpl, float tpp, float tll)
{
    float num = tpl + 1e-5f;
    float den = 0.f;
    float a = 1.f;
    #pragma unroll
    for (int d = 0; d < 5; d++) {
        float bcoef = -(2.f * a - 1.f);
        den += 1.f / (a * (tpp + tll) + bcoef * tpl + 1e-5f);
        a *= 2.f;
    }
    return num * den * 0.2f;
}

__global__ void zero_sums_kernel()
{
    int i = blockIdx.x * blockDim.x + threadIdx.x;
    if (i < BB * 3 * CC) g_sums[i] = 0.f;
}

// ----------------------------------------------------------------------
// per-pixel spatial attention + per-(b,c) partial sums
// ----------------------------------------------------------------------
__global__ __launch_bounds__(256) void attn_stats_kernel()
{
    __shared__ float s_sum[3 * CC];
    const int b = blockIdx.y;
    const int lane = threadIdx.x & 31;
    const int warp = threadIdx.x >> 5;

    for (int i = threadIdx.x; i < 3 * CC; i += 256) s_sum[i] = 0.f;
    __syncthreads();

    float aPL[3] = {0, 0, 0}, aPP[3] = {0, 0, 0}, aLL[3] = {0, 0, 0};
    int pix0 = blockIdx.x * 128 + warp * 16;

    for (int t = 0; t < 16; ++t) {
        int pix = pix0 + t;
        const float* qp = g_q + ((size_t)b * NPIX + pix) * CC;
        const float* kp = g_k + ((size_t)b * NPIX + pix) * CC;
        float tpl = 0.f, tpp = 0.f, tll = 0.f;
        #pragma unroll
        for (int s = 0; s < 3; s++) {
            float qv = qp[lane + s * 32];
            float kv = kp[lane + s * 32];
            float pl = qv * kv, pp = qv * qv, ll = kv * kv;
            aPL[s] += pl; aPP[s] += pp; aLL[s] += ll;
            tpl += pl; tpp += pp; tll += ll;
        }
        #pragma unroll
        for (int off = 16; off > 0; off >>= 1) {
            tpl += __shfl_xor_sync(0xffffffffu, tpl, off);
            tpp += __shfl_xor_sync(0xffffffffu, tpp, off);
            tll += __shfl_xor_sync(0xffffffffu, tll, off);
        }
        if (lane == 0)
            g_spat[(size_t)b * NPIX + pix] = ftan(tpl, tpp, tll);
    }

    #pragma unroll
    for (int s = 0; s < 3; s++) {
        int c = lane + s * 32;
        atomicAdd(&s_sum[0 * CC + c], aPL[s]);
        atomicAdd(&s_sum[1 * CC + c], aPP[s]);
        atomicAdd(&s_sum[2 * CC + c], aLL[s]);
    }
    __syncthreads();
    for (int i = threadIdx.x; i < 3 * CC; i += 256)
        atomicAdd(&g_sums[b * 3 * CC + i], s_sum[i]);
}

__global__ void chan_att_kernel()
{
    int i = blockIdx.x * blockDim.x + threadIdx.x;
    if (i < BB * CC) {
        int b = i / CC, c = i % CC;
        float tpl = g_sums[b * 3 * CC + 0 * CC + c];
        float tpp = g_sums[b * 3 * CC + 1 * CC + c];
        float tll = g_sums[b * 3 * CC + 2 * CC + c];
        g_chan[i] = ftan(tpl, tpp, tll);
    }
}

// ----------------------------------------------------------------------
// final: out = BN(0.5*(att_chan + att_spat) * v)
// ----------------------------------------------------------------------
__global__ __launch_bounds__(256) void final_kernel(
    const float* __restrict__ gam, const float* __restrict__ bet,
    const float* __restrict__ mu, const float* __restrict__ var,
    float* __restrict__ out)
{
    size_t i = (size_t)blockIdx.x * 256 + threadIdx.x;   // float4 index
    size_t e = i * 4;
    if (e >= (size_t)BB * NPIX * CC) return;
    int c = (int)(e % CC);
    size_t pix = e / CC;
    int b = (int)(pix >> 14);
    float as = g_spat[pix];
    float4 vv4 = *reinterpret_cast<const float4*>(g_v + e);
    float vin[4] = {vv4.x, vv4.y, vv4.z, vv4.w};
    float res[4];
    #pragma unroll
    for (int j = 0; j < 4; j++) {
        int cj = c + j;
        float val = 0.5f * (g_chan[b * CC + cj] + as) * vin[j];
        res[j] = (val - mu[cj]) * rsqrtf(var[cj] + 1e-5f) * gam[cj] + bet[cj];
    }
    *reinterpret_cast<float4*>(out + e) = make_float4(res[0], res[1], res[2], res[3]);
}

// ----------------------------------------------------------------------
extern "C" void kernel_launch(void* const* d_in, const int* in_sizes, int n_in,
                              void* d_out, int out_size)
{
    const float* x1 = (const float*)d_in[0];
    const float* x2 = (const float*)d_in[1];
    const float* x3 = (const float*)d_in[2];
    const float* wq = (const float*)d_in[3];
    const float* gq = (const float*)d_in[4];
    const float* bq = (const float*)d_in[5];
    const float* mq = (const float*)d_in[6];
    const float* vq = (const float*)d_in[7];
    const float* wk = (const float*)d_in[8];
    const float* gk = (const float*)d_in[9];
    const float* bk = (const float*)d_in[10];
    const float* mk = (const float*)d_in[11];
    const float* vk = (const float*)d_in[12];
    const float* wv = (const float*)d_in[13];
    const float* gv = (const float*)d_in[14];
    const float* bv = (const float*)d_in[15];
    const float* mv = (const float*)d_in[16];
    const float* vv = (const float*)d_in[17];
    const float* gn  = (const float*)d_in[18];
    const float* bnb = (const float*)d_in[19];
    const float* mn  = (const float*)d_in[20];
    const float* vn  = (const float*)d_in[21];
    float* out = (float*)d_out;

    float *qp, *kp, *vp;
    __nv_bfloat16 *wbq, *wbk, *wbv;
    cudaGetSymbolAddress((void**)&qp, g_q);
    cudaGetSymbolAddress((void**)&kp, g_k);
    cudaGetSymbolAddress((void**)&vp, g_v);
    cudaGetSymbolAddress((void**)&wbq, g_wbq);
    cudaGetSymbolAddress((void**)&wbk, g_wbk);
    cudaGetSymbolAddress((void**)&wbv, g_wbv);

    cudaFuncSetAttribute(conv_mma_kernel,
                         cudaFuncAttributeMaxDynamicSharedMemorySize, SMEM_CONV);

    const int WT_BLOCKS = (9 * CC * CC + 255) / 256;

    // ordering keeps ncu's capture slot on a conv launch
    zero_sums_kernel<<<(BB * 3 * CC + 255) / 256, 256>>>();
    wtrans_kernel<<<WT_BLOCKS, 256>>>(wq, wbq);
    wtrans_kernel<<<WT_BLOCKS, 256>>>(wk, wbk);
    wtrans_kernel<<<WT_BLOCKS, 256>>>(wv, wbv);

    dim3 gridC(HH, BB);   // one CTA per image row
    conv_mma_kernel<<<gridC, 256, SMEM_CONV>>>(x1, wbq, gq, bq, mq, vq, qp);
    conv_mma_kernel<<<gridC, 256, SMEM_CONV>>>(x2, wbk, gk, bk, mk, vk, kp);
    conv_mma_kernel<<<gridC, 256, SMEM_CONV>>>(x3, wbv, gv, bv, mv, vv, vp);

    dim3 gridB(128, BB);
    attn_stats_kernel<<<gridB, 256>>>();
    chan_att_kernel<<<(BB * CC + 255) / 256, 256>>>();

    size_t n4 = (size_t)BB * NPIX * CC / 4;
    final_kernel<<<(unsigned)((n4 + 255) / 256), 256>>>(gn, bnb, mn, vn, out);
}